// round 12
// baseline (speedup 1.0000x reference)
#include <cuda_runtime.h>
#include <cstdint>

// Fixed problem shape
#define NPIX      102400            // B*H*W = 4*160*160
#define HW        25600             // H*W
#define NV        1024
#define OUT_ELEMS (NV * 2 * 32 * 32)   // 2,097,152 floats = 8 MB

// Gaussian in bin coordinates: t = (x+1)*16 - 0.5, sigma_bins = 0.8
// log2-space coefficient: -0.5/(0.8^2) * log2(e)
#define CEXP   (-1.12710546f)
#define SKIPTH (1e-4f)

__device__ int g_sizes[NV];

// ---------------------------------------------------------------------------
// Kernel 1: segment bincount (g_sizes zeroed by memset node beforehand)
// ---------------------------------------------------------------------------
__global__ void count_kernel(const int* __restrict__ seg) {
    int n = blockIdx.x * blockDim.x + threadIdx.x;
    if (n < NPIX) atomicAdd(&g_sizes[seg[n]], 1);
}

// ---------------------------------------------------------------------------
// Predicated vector reduction: issue red.v4 only if gate > SKIPTH.
// ---------------------------------------------------------------------------
__device__ __forceinline__ void red4p(float gate, float* p,
                                      float a, float b, float c, float d) {
    asm volatile(
        "{\n\t"
        ".reg .pred pg;\n\t"
        "setp.gt.f32 pg, %0, %1;\n\t"
        "@pg red.global.add.v4.f32 [%2], {%3,%4,%5,%6};\n\t"
        "}"
        :: "f"(gate), "f"(SKIPTH), "l"(p), "f"(a), "f"(b), "f"(c), "f"(d)
        : "memory");
}

// ---------------------------------------------------------------------------
// Kernel 2: windowed Parzen scatter into d_out, normalization folded in.
// (R4 structure — best measured. REDG per-lane dispatch is the floor;
// SKIPTH=1e-4 shrinks effective support radius ~3.7 -> ~3.4 bins.)
// ---------------------------------------------------------------------------
__global__ void __launch_bounds__(256)
hist_kernel(const int* __restrict__ seg,
            const int* __restrict__ byx,
            const float* __restrict__ grad,
            float* __restrict__ out) {
    int n = blockIdx.x * blockDim.x + threadIdx.x;
    if (n >= NPIX) return;

    int v = seg[n];
    float inv = 1.0f / (float)__ldg(&g_sizes[v]);   // den = sizes*(P/32)^2 = sizes

    // bin coordinates: t = (x+1)*16 - 0.5
    float t0 = (float)byx[NPIX + n]     * 0.2f - 0.5f;
    float t1 = (float)byx[2 * NPIX + n] * 0.2f - 0.5f;
    int   b  = n / HW;
    int   hw = n - b * HW;
    float t2 = grad[b * 2 * HW + hw]      * 16.f + 15.5f;
    float t3 = grad[b * 2 * HW + HW + hw] * 16.f + 15.5f;

    float* base0 = out + (size_t)v * 2048;

    // ---- pair 0: dims (0,1) — always in range ----
    {
        int lo0 = min(26, max(0, __float2int_rd(t0) - 2));
        float w0[6];
#pragma unroll
        for (int k = 0; k < 6; k++) {
            float d = t0 - (float)(lo0 + k);
            w0[k] = exp2f(CEXP * d * d);
        }
        int qa1 = min(20, max(0, (__float2int_rd(t1) - 3) & ~3));
        float w1[12];
#pragma unroll
        for (int k = 0; k < 12; k++) {
            float d = t1 - (float)(qa1 + k);
            w1[k] = exp2f(CEXP * d * d);
        }
        float m0 = fmaxf(fmaxf(w1[0], w1[1]),  fmaxf(w1[2],  w1[3]));
        float m1 = fmaxf(fmaxf(w1[4], w1[5]),  fmaxf(w1[6],  w1[7]));
        float m2 = fmaxf(fmaxf(w1[8], w1[9]),  fmaxf(w1[10], w1[11]));
#pragma unroll
        for (int p = 0; p < 6; p++) {
            float wr = w0[p];
            float a  = wr * inv;
            float* row = base0 + (lo0 + p) * 32 + qa1;
            red4p(wr * m0, row,     a * w1[0], a * w1[1], a * w1[2],  a * w1[3]);
            red4p(wr * m1, row + 4, a * w1[4], a * w1[5], a * w1[6],  a * w1[7]);
            red4p(wr * m2, row + 8, a * w1[8], a * w1[9], a * w1[10], a * w1[11]);
        }
    }

    // ---- pair 1: dims (2,3) — grads can fall outside all bins -> skip ----
    if (t2 > -3.5f && t2 < 34.5f && t3 > -3.5f && t3 < 34.5f) {
        int lo2 = min(26, max(0, __float2int_rd(t2) - 2));
        float w2[6];
#pragma unroll
        for (int k = 0; k < 6; k++) {
            float d = t2 - (float)(lo2 + k);
            w2[k] = exp2f(CEXP * d * d);
        }
        int qa3 = min(20, max(0, (__float2int_rd(t3) - 3) & ~3));
        float w3[12];
#pragma unroll
        for (int k = 0; k < 12; k++) {
            float d = t3 - (float)(qa3 + k);
            w3[k] = exp2f(CEXP * d * d);
        }
        float m0 = fmaxf(fmaxf(w3[0], w3[1]),  fmaxf(w3[2],  w3[3]));
        float m1 = fmaxf(fmaxf(w3[4], w3[5]),  fmaxf(w3[6],  w3[7]));
        float m2 = fmaxf(fmaxf(w3[8], w3[9]),  fmaxf(w3[10], w3[11]));
        float* base1 = base0 + 1024;
#pragma unroll
        for (int p = 0; p < 6; p++) {
            float wr = w2[p];
            float a  = wr * inv;
            float* row = base1 + (lo2 + p) * 32 + qa3;
            red4p(wr * m0, row,     a * w3[0], a * w3[1], a * w3[2],  a * w3[3]);
            red4p(wr * m1, row + 4, a * w3[4], a * w3[5], a * w3[6],  a * w3[7]);
            red4p(wr * m2, row + 8, a * w3[8], a * w3[9], a * w3[10], a * w3[11]);
        }
    }
}

// ---------------------------------------------------------------------------
extern "C" void kernel_launch(void* const* d_in, const int* in_sizes, int n_in,
                              void* d_out, int out_size) {
    const int*   seg  = (const int*)d_in[0];
    const int*   byx  = (const int*)d_in[1];
    const float* grad = (const float*)d_in[2];
    float*       out  = (float*)d_out;

    // zero output + counters via memset nodes (graph-capturable, no kernel)
    cudaMemsetAsync(out, 0, OUT_ELEMS * sizeof(float));
    void* sizes_ptr = nullptr;
    cudaGetSymbolAddress(&sizes_ptr, g_sizes);
    cudaMemsetAsync(sizes_ptr, 0, NV * sizeof(int));

    count_kernel<<<(NPIX + 255) / 256, 256>>>(seg);
    hist_kernel<<<(NPIX + 255) / 256, 256>>>(seg, byx, grad, out);
}

// round 13
// speedup vs baseline: 1.1180x; 1.1180x over previous
#include <cuda_runtime.h>
#include <cstdint>

// Fixed problem shape
#define NPIX      102400            // B*H*W = 4*160*160
#define HW        25600             // H*W
#define NV        1024
#define OUT_ELEMS (NV * 2 * 32 * 32)   // 2,097,152 floats; 524,288 float4
#define NBLK      400               // 400 x 256 threads = NPIX exactly

// Gaussian in bin coordinates: t = (x+1)*16 - 0.5, sigma_bins = 0.8
// log2-space coefficient: -0.5/(0.8^2) * log2(e)
#define CEXP   (-1.12710546f)
#define SKIPTH (1e-4f)

__device__ int      g_sizes[NV];
__device__ unsigned g_bar[2];     // arrival counters (self-restoring)
__device__ unsigned g_left[2];    // exit counters   (self-restoring)

// ---------------------------------------------------------------------------
// Software grid barrier. All NBLK blocks are co-resident (launch_bounds(256,3)
// -> capacity 3*148=444 >= 400), so spinning is deadlock-free.
// Self-restoring: the 400th leaver resets both counters; those stores are
// visible at kernel end, so every launch/replay starts from zero state.
// Each barrier index is used once per launch -> no reuse race.
// ---------------------------------------------------------------------------
__device__ __forceinline__ void grid_barrier(int i) {
    __syncthreads();
    if (threadIdx.x == 0) {
        __threadfence();                       // publish phase writes
        atomicAdd(&g_bar[i], 1u);
        unsigned r;
        do {
            asm volatile("ld.acquire.gpu.global.u32 %0, [%1];"
                         : "=r"(r) : "l"(&g_bar[i]));
        } while (r < NBLK);
        unsigned old = atomicAdd(&g_left[i], 1u);
        if (old == NBLK - 1) { g_bar[i] = 0; g_left[i] = 0; }
    }
    __syncthreads();
}

// ---------------------------------------------------------------------------
// Predicated vector reduction: issue red.v4 only if gate > SKIPTH.
// ---------------------------------------------------------------------------
__device__ __forceinline__ void red4p(float gate, float* p,
                                      float a, float b, float c, float d) {
    asm volatile(
        "{\n\t"
        ".reg .pred pg;\n\t"
        "setp.gt.f32 pg, %0, %1;\n\t"
        "@pg red.global.add.v4.f32 [%2], {%3,%4,%5,%6};\n\t"
        "}"
        :: "f"(gate), "f"(SKIPTH), "l"(p), "f"(a), "f"(b), "f"(c), "f"(d)
        : "memory");
}

// ---------------------------------------------------------------------------
// Fused kernel: zero -> barrier -> count -> barrier -> Parzen scatter.
// hist phase = R12 structure (SKIPTH 1e-4, measured 16.2us, REDG floor).
// ---------------------------------------------------------------------------
__global__ void __launch_bounds__(256, 3)
fused_kernel(const int* __restrict__ seg,
             const int* __restrict__ byx,
             const float* __restrict__ grad,
             float* __restrict__ out) {
    int n = blockIdx.x * 256 + threadIdx.x;    // 0..NPIX-1 exactly

    // ---- phase 0: zero output + counters ----
    {
        float4* o4 = reinterpret_cast<float4*>(out);
        float4 z = make_float4(0.f, 0.f, 0.f, 0.f);
#pragma unroll
        for (int i = n; i < OUT_ELEMS / 4; i += NPIX) o4[i] = z;
        if (n < NV) g_sizes[n] = 0;
    }
    grid_barrier(0);

    // ---- phase 1: segment bincount ----
    int v = seg[n];
    atomicAdd(&g_sizes[v], 1);
    grid_barrier(1);

    // ---- phase 2: windowed Parzen scatter ----
    float inv = 1.0f / (float)g_sizes[v];      // den = sizes*(P/32)^2 = sizes

    float t0 = (float)byx[NPIX + n]     * 0.2f - 0.5f;
    float t1 = (float)byx[2 * NPIX + n] * 0.2f - 0.5f;
    int   b  = n / HW;
    int   hw = n - b * HW;
    float t2 = grad[b * 2 * HW + hw]      * 16.f + 15.5f;
    float t3 = grad[b * 2 * HW + HW + hw] * 16.f + 15.5f;

    float* base0 = out + (size_t)v * 2048;

    // pair 0: dims (0,1) — always in range
    {
        int lo0 = min(26, max(0, __float2int_rd(t0) - 2));
        float w0[6];
#pragma unroll
        for (int k = 0; k < 6; k++) {
            float d = t0 - (float)(lo0 + k);
            w0[k] = exp2f(CEXP * d * d);
        }
        int qa1 = min(20, max(0, (__float2int_rd(t1) - 3) & ~3));
        float w1[12];
#pragma unroll
        for (int k = 0; k < 12; k++) {
            float d = t1 - (float)(qa1 + k);
            w1[k] = exp2f(CEXP * d * d);
        }
        float m0 = fmaxf(fmaxf(w1[0], w1[1]),  fmaxf(w1[2],  w1[3]));
        float m1 = fmaxf(fmaxf(w1[4], w1[5]),  fmaxf(w1[6],  w1[7]));
        float m2 = fmaxf(fmaxf(w1[8], w1[9]),  fmaxf(w1[10], w1[11]));
#pragma unroll
        for (int p = 0; p < 6; p++) {
            float wr = w0[p];
            float a  = wr * inv;
            float* row = base0 + (lo0 + p) * 32 + qa1;
            red4p(wr * m0, row,     a * w1[0], a * w1[1], a * w1[2],  a * w1[3]);
            red4p(wr * m1, row + 4, a * w1[4], a * w1[5], a * w1[6],  a * w1[7]);
            red4p(wr * m2, row + 8, a * w1[8], a * w1[9], a * w1[10], a * w1[11]);
        }
    }

    // pair 1: dims (2,3) — grads can fall outside all bins -> skip
    if (t2 > -3.5f && t2 < 34.5f && t3 > -3.5f && t3 < 34.5f) {
        int lo2 = min(26, max(0, __float2int_rd(t2) - 2));
        float w2[6];
#pragma unroll
        for (int k = 0; k < 6; k++) {
            float d = t2 - (float)(lo2 + k);
            w2[k] = exp2f(CEXP * d * d);
        }
        int qa3 = min(20, max(0, (__float2int_rd(t3) - 3) & ~3));
        float w3[12];
#pragma unroll
        for (int k = 0; k < 12; k++) {
            float d = t3 - (float)(qa3 + k);
            w3[k] = exp2f(CEXP * d * d);
        }
        float m0 = fmaxf(fmaxf(w3[0], w3[1]),  fmaxf(w3[2],  w3[3]));
        float m1 = fmaxf(fmaxf(w3[4], w3[5]),  fmaxf(w3[6],  w3[7]));
        float m2 = fmaxf(fmaxf(w3[8], w3[9]),  fmaxf(w3[10], w3[11]));
        float* base1 = base0 + 1024;
#pragma unroll
        for (int p = 0; p < 6; p++) {
            float wr = w2[p];
            float a  = wr * inv;
            float* row = base1 + (lo2 + p) * 32 + qa3;
            red4p(wr * m0, row,     a * w3[0], a * w3[1], a * w3[2],  a * w3[3]);
            red4p(wr * m1, row + 4, a * w3[4], a * w3[5], a * w3[6],  a * w3[7]);
            red4p(wr * m2, row + 8, a * w3[8], a * w3[9], a * w3[10], a * w3[11]);
        }
    }
}

// ---------------------------------------------------------------------------
extern "C" void kernel_launch(void* const* d_in, const int* in_sizes, int n_in,
                              void* d_out, int out_size) {
    const int*   seg  = (const int*)d_in[0];
    const int*   byx  = (const int*)d_in[1];
    const float* grad = (const float*)d_in[2];
    float*       out  = (float*)d_out;

    fused_kernel<<<NBLK, 256>>>(seg, byx, grad, out);
}

// round 14
// speedup vs baseline: 1.1945x; 1.0684x over previous
#include <cuda_runtime.h>
#include <cstdint>

// Fixed problem shape
#define NPIX      102400            // B*H*W = 4*160*160
#define HW        25600             // H*W
#define NV        1024
#define OUT_ELEMS (NV * 2 * 32 * 32)   // 524,288 float4
#define NBLK      400               // 400 x 256 = NPIX exactly

// Gaussian in bin coordinates: t = (x+1)*16 - 0.5, sigma_bins = 0.8
#define CEXP   (-1.12710546f)
#define SKIPTH (1e-4f)

// Self-restoring state: zero at module load; last-finishing block restores
// g_sizes/g_done to zero each launch, so graph replays are deterministic.
__device__ int      g_sizes[NV];
__device__ unsigned g_bar;
__device__ unsigned g_left;
__device__ unsigned g_done;

// ---------------------------------------------------------------------------
// Single software grid barrier (all 400 blocks co-resident: 3*148=444 >= 400).
// Self-restoring via exit counter.
// ---------------------------------------------------------------------------
__device__ __forceinline__ void grid_barrier() {
    __syncthreads();
    if (threadIdx.x == 0) {
        __threadfence();
        atomicAdd(&g_bar, 1u);
        unsigned r;
        do {
            asm volatile("ld.acquire.gpu.global.u32 %0, [%1];"
                         : "=r"(r) : "l"(&g_bar));
        } while (r < NBLK);
        unsigned old = atomicAdd(&g_left, 1u);
        if (old == NBLK - 1) { g_bar = 0; g_left = 0; }
    }
    __syncthreads();
}

__device__ __forceinline__ void red4p(float gate, float* p,
                                      float a, float b, float c, float d) {
    asm volatile(
        "{\n\t"
        ".reg .pred pg;\n\t"
        "setp.gt.f32 pg, %0, %1;\n\t"
        "@pg red.global.add.v4.f32 [%2], {%3,%4,%5,%6};\n\t"
        "}"
        :: "f"(gate), "f"(SKIPTH), "l"(p), "f"(a), "f"(b), "f"(c), "f"(d)
        : "memory");
}

// ---------------------------------------------------------------------------
// Fused kernel: [zero out + count + prefetch] -> barrier -> Parzen scatter.
// g_sizes enters this kernel already zero (self-restored by previous call /
// module load), so counting needs no prior zeroing barrier.
// ---------------------------------------------------------------------------
__global__ void __launch_bounds__(256, 3)
fused_kernel(const int* __restrict__ seg,
             const int* __restrict__ byx,
             const float* __restrict__ grad,
             float* __restrict__ out) {
    int n = blockIdx.x * 256 + threadIdx.x;    // 0..NPIX-1

    // ---- phase 0: count into (already-zero) g_sizes, zero output,
    //               prefetch + transform inputs into registers ----
    int v = seg[n];
    atomicAdd(&g_sizes[v], 1);

    float t0 = (float)byx[NPIX + n]     * 0.2f - 0.5f;
    float t1 = (float)byx[2 * NPIX + n] * 0.2f - 0.5f;
    int   b  = n / HW;
    int   hw = n - b * HW;
    float t2 = grad[b * 2 * HW + hw]      * 16.f + 15.5f;
    float t3 = grad[b * 2 * HW + HW + hw] * 16.f + 15.5f;

    {
        float4* o4 = reinterpret_cast<float4*>(out);
        float4 z = make_float4(0.f, 0.f, 0.f, 0.f);
#pragma unroll
        for (int i = n; i < OUT_ELEMS / 4; i += NPIX) o4[i] = z;
    }

    grid_barrier();

    // ---- phase 1: windowed Parzen scatter ----
    float inv = 1.0f / (float)g_sizes[v];      // den = sizes*(P/32)^2 = sizes
    float* base0 = out + (size_t)v * 2048;

    // pair 0: dims (0,1) — always in range
    {
        int lo0 = min(26, max(0, __float2int_rd(t0) - 2));
        float w0[6];
#pragma unroll
        for (int k = 0; k < 6; k++) {
            float d = t0 - (float)(lo0 + k);
            w0[k] = exp2f(CEXP * d * d);
        }
        int qa1 = min(20, max(0, (__float2int_rd(t1) - 3) & ~3));
        float w1[12];
#pragma unroll
        for (int k = 0; k < 12; k++) {
            float d = t1 - (float)(qa1 + k);
            w1[k] = exp2f(CEXP * d * d);
        }
        float m0 = fmaxf(fmaxf(w1[0], w1[1]),  fmaxf(w1[2],  w1[3]));
        float m1 = fmaxf(fmaxf(w1[4], w1[5]),  fmaxf(w1[6],  w1[7]));
        float m2 = fmaxf(fmaxf(w1[8], w1[9]),  fmaxf(w1[10], w1[11]));
#pragma unroll
        for (int p = 0; p < 6; p++) {
            float wr = w0[p];
            float a  = wr * inv;
            float* row = base0 + (lo0 + p) * 32 + qa1;
            red4p(wr * m0, row,     a * w1[0], a * w1[1], a * w1[2],  a * w1[3]);
            red4p(wr * m1, row + 4, a * w1[4], a * w1[5], a * w1[6],  a * w1[7]);
            red4p(wr * m2, row + 8, a * w1[8], a * w1[9], a * w1[10], a * w1[11]);
        }
    }

    // pair 1: dims (2,3) — grads can fall outside all bins -> skip
    if (t2 > -3.5f && t2 < 34.5f && t3 > -3.5f && t3 < 34.5f) {
        int lo2 = min(26, max(0, __float2int_rd(t2) - 2));
        float w2[6];
#pragma unroll
        for (int k = 0; k < 6; k++) {
            float d = t2 - (float)(lo2 + k);
            w2[k] = exp2f(CEXP * d * d);
        }
        int qa3 = min(20, max(0, (__float2int_rd(t3) - 3) & ~3));
        float w3[12];
#pragma unroll
        for (int k = 0; k < 12; k++) {
            float d = t3 - (float)(qa3 + k);
            w3[k] = exp2f(CEXP * d * d);
        }
        float m0 = fmaxf(fmaxf(w3[0], w3[1]),  fmaxf(w3[2],  w3[3]));
        float m1 = fmaxf(fmaxf(w3[4], w3[5]),  fmaxf(w3[6],  w3[7]));
        float m2 = fmaxf(fmaxf(w3[8], w3[9]),  fmaxf(w3[10], w3[11]));
        float* base1 = base0 + 1024;
#pragma unroll
        for (int p = 0; p < 6; p++) {
            float wr = w2[p];
            float a  = wr * inv;
            float* row = base1 + (lo2 + p) * 32 + qa3;
            red4p(wr * m0, row,     a * w3[0], a * w3[1], a * w3[2],  a * w3[3]);
            red4p(wr * m1, row + 4, a * w3[4], a * w3[5], a * w3[6],  a * w3[7]);
            red4p(wr * m2, row + 8, a * w3[8], a * w3[9], a * w3[10], a * w3[11]);
        }
    }

    // ---- exit: last block restores g_sizes/g_done to zero (no spinning).
    // Every block increments only after all its threads finished reading
    // g_sizes, so the restore cannot race those reads.
    __syncthreads();
    __shared__ bool s_last;
    if (threadIdx.x == 0) {
        unsigned old = atomicAdd(&g_done, 1u);
        s_last = (old == NBLK - 1);
    }
    __syncthreads();
    if (s_last) {
#pragma unroll
        for (int i = threadIdx.x; i < NV; i += 256) g_sizes[i] = 0;
        if (threadIdx.x == 0) g_done = 0;
    }
}

// ---------------------------------------------------------------------------
extern "C" void kernel_launch(void* const* d_in, const int* in_sizes, int n_in,
                              void* d_out, int out_size) {
    const int*   seg  = (const int*)d_in[0];
    const int*   byx  = (const int*)d_in[1];
    const float* grad = (const float*)d_in[2];
    float*       out  = (float*)d_out;

    fused_kernel<<<NBLK, 256>>>(seg, byx, grad, out);
}